// round 4
// baseline (speedup 1.0000x reference)
#include <cuda_runtime.h>
#include <math.h>

// Problem constants
#define B_    2
#define L_    2048
#define DM    1024
#define DI    2048
#define DS    16
#define DR    64
#define XD    96            // DR + 2*DS
#define MTOK  (B_ * L_)     // 4096 tokens

// Scratch (device globals: allocation-free, loaded with the module)
__device__ float g_xz[(size_t)MTOK * (2 * DI)];   // [M, 4096]  in-proj output (x_p | z)
__device__ float g_xc[(size_t)MTOK * DI];         // [M, 2048]  conv+silu output
__device__ float g_xdbl[(size_t)MTOK * XD];       // [M, 96]    (dt_raw | B | C)
__device__ float g_delta[(size_t)MTOK * DI];      // [M, 2048]  softplus(dt)
__device__ float g_g[(size_t)MTOK * DI];          // [M, 2048]  gated scan output

// ---------------------------------------------------------------------------
// Generic tiled SGEMM: C[M,N] = A[M,K] @ B[N,K]^T   (both K-contiguous, "NT")
// EPI=0: plain store. EPI=1: += bias[n], softplus.
// Requires M % BM == 0 and K % BK == 0 (true for all call sites); N guarded.
// ---------------------------------------------------------------------------
template <int BM, int BN, int BK, int TM, int TN, int EPI>
__global__ void __launch_bounds__(256) sgemm_nt(
    const float* __restrict__ A, const float* __restrict__ Bw,
    float* __restrict__ C, int M, int N, int K,
    int lda, int ldb, int ldc, const float* __restrict__ bias)
{
    __shared__ float As[BK][BM + 1];
    __shared__ float Bs[BK][BN + 1];

    const int tid = threadIdx.x;
    const int m0 = blockIdx.y * BM;
    const int n0 = blockIdx.x * BN;
    const int tx = tid % (BN / TN);
    const int ty = tid / (BN / TN);

    float acc[TM][TN];
#pragma unroll
    for (int i = 0; i < TM; i++)
#pragma unroll
        for (int j = 0; j < TN; j++) acc[i][j] = 0.f;

    for (int k0 = 0; k0 < K; k0 += BK) {
        // Load A tile (transposed into smem)
#pragma unroll
        for (int i = tid; i < BM * BK; i += 256) {
            int m = i / BK, k = i % BK;
            As[k][m] = A[(size_t)(m0 + m) * lda + k0 + k];
        }
        // Load B tile (transposed), guard N
#pragma unroll
        for (int i = tid; i < BN * BK; i += 256) {
            int nn = i / BK, k = i % BK;
            int gn = n0 + nn;
            Bs[k][nn] = (gn < N) ? Bw[(size_t)gn * ldb + k0 + k] : 0.f;
        }
        __syncthreads();

#pragma unroll
        for (int kk = 0; kk < BK; kk++) {
            float a[TM], b[TN];
#pragma unroll
            for (int i = 0; i < TM; i++) a[i] = As[kk][ty * TM + i];
#pragma unroll
            for (int j = 0; j < TN; j++) b[j] = Bs[kk][tx * TN + j];
#pragma unroll
            for (int i = 0; i < TM; i++)
#pragma unroll
                for (int j = 0; j < TN; j++)
                    acc[i][j] = fmaf(a[i], b[j], acc[i][j]);
        }
        __syncthreads();
    }

#pragma unroll
    for (int i = 0; i < TM; i++) {
        int gm = m0 + ty * TM + i;
#pragma unroll
        for (int j = 0; j < TN; j++) {
            int gn = n0 + tx * TN + j;
            if (gn < N) {
                float v = acc[i][j];
                if (EPI == 1) {
                    v += bias[gn];
                    // softplus
                    v = (v > 20.f) ? v : log1pf(expf(v));
                }
                C[(size_t)gm * ldc + gn] = v;
            }
        }
    }
}

// ---------------------------------------------------------------------------
// Causal depthwise conv1d (W=4) + bias + SiLU.
// reads x_p = g_xz[:, 0:DI], writes g_xc.
// ---------------------------------------------------------------------------
__global__ void conv_silu_kernel(const float* __restrict__ xz,
                                 const float* __restrict__ cw,
                                 const float* __restrict__ cb,
                                 float* __restrict__ xc)
{
    int idx = blockIdx.x * blockDim.x + threadIdx.x;
    if (idx >= MTOK * DI) return;
    int c = idx % DI;
    int t = idx / DI;        // global token index (b*L + l)
    int l = t % L_;

    float s = cb[c];
    const float* w = cw + c * 4;
#pragma unroll
    for (int j = 0; j < 4; j++) {
        int ll = l - 3 + j;
        if (ll >= 0)
            s = fmaf(w[j], xz[(size_t)(t - 3 + j) * (2 * DI) + c], s);
    }
    float sig = 1.f / (1.f + __expf(-s));
    xc[idx] = s * sig;
}

// ---------------------------------------------------------------------------
// Selective scan, fused with y += x*D and gating y *= silu(z).
// Block = 256 threads = 16 channels x 16 states. One block scans 16 channels
// of one batch across all L timesteps. No barriers in the time loop.
// grid = (DI/16, B)
// ---------------------------------------------------------------------------
__global__ void __launch_bounds__(256) scan_kernel(
    const float* __restrict__ xdbl, const float* __restrict__ delta,
    const float* __restrict__ xc,   const float* __restrict__ xz,
    const float* __restrict__ A_log, const float* __restrict__ Dp,
    float* __restrict__ g)
{
    const int b = blockIdx.y;
    const int c = blockIdx.x * 16 + (threadIdx.x >> 4);
    const int n = threadIdx.x & 15;

    const float Av = -__expf(A_log[c * DS + n]);
    const float Dv = Dp[c];

    const float* dptr = delta + (size_t)b * L_ * DI + c;
    const float* xptr = xc    + (size_t)b * L_ * DI + c;
    const float* bptr = xdbl  + (size_t)b * L_ * XD + DR + n;
    const float* cptr = xdbl  + (size_t)b * L_ * XD + DR + DS + n;
    const float* zptr = xz    + (size_t)b * L_ * (2 * DI) + DI + c;
    float*       gptr = g     + (size_t)b * L_ * DI + c;

    float h = 0.f;
    for (int t = 0; t < L_; t++) {
        float dt = *dptr;
        float xv = *xptr;
        float Bv = *bptr;
        float Cv = *cptr;

        float dA = __expf(dt * Av);
        h = fmaf(dA, h, dt * Bv * xv);

        float p = h * Cv;
        p += __shfl_xor_sync(0xffffffffu, p, 8, 16);
        p += __shfl_xor_sync(0xffffffffu, p, 4, 16);
        p += __shfl_xor_sync(0xffffffffu, p, 2, 16);
        p += __shfl_xor_sync(0xffffffffu, p, 1, 16);

        if (n == 0) {
            float y = p + xv * Dv;
            float z = *zptr;
            float sg = 1.f / (1.f + __expf(-z));
            *gptr = y * z * sg;
        }
        dptr += DI; xptr += DI; bptr += XD; cptr += XD;
        zptr += 2 * DI; gptr += DI;
    }
}

// ---------------------------------------------------------------------------
extern "C" void kernel_launch(void* const* d_in, const int* in_sizes, int n_in,
                              void* d_out, int out_size)
{
    const float* x          = (const float*)d_in[0];
    const float* in_proj_w  = (const float*)d_in[1];
    const float* conv_w     = (const float*)d_in[2];
    const float* conv_b     = (const float*)d_in[3];
    const float* x_proj_w   = (const float*)d_in[4];
    const float* dt_proj_w  = (const float*)d_in[5];
    const float* dt_proj_b  = (const float*)d_in[6];
    const float* A_log      = (const float*)d_in[7];
    const float* Dp         = (const float*)d_in[8];
    const float* out_proj_w = (const float*)d_in[9];
    float* out = (float*)d_out;

    float *xz, *xc, *xdbl, *delta, *gg;
    cudaGetSymbolAddress((void**)&xz,    g_xz);
    cudaGetSymbolAddress((void**)&xc,    g_xc);
    cudaGetSymbolAddress((void**)&xdbl,  g_xdbl);
    cudaGetSymbolAddress((void**)&delta, g_delta);
    cudaGetSymbolAddress((void**)&gg,    g_g);

    // 1) xz = x @ in_proj_w^T   [4096,1024] x [4096,1024]^T -> [4096,4096]
    sgemm_nt<128, 128, 16, 8, 8, 0><<<dim3(32, 32), 256>>>(
        x, in_proj_w, xz, MTOK, 2 * DI, DM, DM, DM, 2 * DI, nullptr);

    // 2) causal depthwise conv + SiLU -> xc
    conv_silu_kernel<<<(MTOK * DI + 255) / 256, 256>>>(xz, conv_w, conv_b, xc);

    // 3) x_dbl = xc @ x_proj_w^T  [4096,2048] x [96,2048]^T -> [4096,96]
    sgemm_nt<64, 96, 16, 4, 6, 0><<<dim3(1, 64), 256>>>(
        xc, x_proj_w, xdbl, MTOK, XD, DI, DI, DI, XD, nullptr);

    // 4) delta = softplus(x_dbl[:, :64] @ dt_proj_w^T + b)  -> [4096,2048]
    sgemm_nt<128, 128, 16, 8, 8, 1><<<dim3(16, 32), 256>>>(
        xdbl, dt_proj_w, delta, MTOK, DI, DR, XD, DR, DI, dt_proj_b);

    // 5) selective scan + skip(D) + gating silu(z) -> gg
    scan_kernel<<<dim3(DI / 16, B_), 256>>>(xdbl, delta, xc, xz, A_log, Dp, gg);

    // 6) out = gg @ out_proj_w^T  [4096,2048] x [1024,2048]^T -> [4096,1024]
    sgemm_nt<128, 128, 16, 8, 8, 0><<<dim3(8, 32), 256>>>(
        gg, out_proj_w, out, MTOK, DM, DI, DI, DI, DM, nullptr);
}

// round 6
// speedup vs baseline: 1.6030x; 1.6030x over previous
#include <cuda_runtime.h>
#include <math.h>

// Problem constants
#define B_    2
#define L_    2048
#define DM    1024
#define DI    2048
#define DS    16
#define DR    64
#define XD    96            // DR + 2*DS
#define MTOK  (B_ * L_)     // 4096 tokens

// Scratch (device globals: allocation-free)
__device__ float g_xz[(size_t)MTOK * (2 * DI)];   // [M, 4096]  in-proj output (x_p | z)
__device__ float g_xc[(size_t)MTOK * DI];         // [M, 2048]  conv+silu output
__device__ float g_xdbl[(size_t)MTOK * XD];       // [M, 96]    (dt_raw | B | C)
__device__ float g_delta[(size_t)MTOK * DI];      // [M, 2048]  softplus(dt)
__device__ float g_g[(size_t)MTOK * DI];          // [M, 2048]  gated scan output

// ---------------------------------------------------------------------------
// TF32 helpers
// ---------------------------------------------------------------------------
__device__ __forceinline__ unsigned f2tf32(float f) {
    unsigned r;
    asm("cvt.rna.tf32.f32 %0, %1;" : "=r"(r) : "f"(f));
    return r;
}

__device__ __forceinline__ void mma_tf32(float (&d)[4], const unsigned (&a)[4],
                                         const unsigned (&b)[2]) {
    asm volatile(
        "mma.sync.aligned.m16n8k8.row.col.f32.tf32.tf32.f32 "
        "{%0,%1,%2,%3}, {%4,%5,%6,%7}, {%8,%9}, {%0,%1,%2,%3};\n"
        : "+f"(d[0]), "+f"(d[1]), "+f"(d[2]), "+f"(d[3])
        : "r"(a[0]), "r"(a[1]), "r"(a[2]), "r"(a[3]),
          "r"(b[0]), "r"(b[1]));
}

// ---------------------------------------------------------------------------
// TF32 tensor-core GEMM: C[M,N] = A[M,K] @ B[N,K]^T  (both K-contiguous, "NT")
// 256 threads = 8 warps in WRM x WRN grid. Warp tile (BM/WRM) x (BN/WRN).
// EPI=0: plain store. EPI=1: += bias[n], softplus.
// Requires: M % BM == 0, K % BK == 0, BK multiple of 8, N multiple of 8.
// ---------------------------------------------------------------------------
template <int BM, int BN, int BK, int WRM, int WRN, int EPI>
__global__ void __launch_bounds__(256) mma_gemm_nt(
    const float* __restrict__ A, const float* __restrict__ Bw,
    float* __restrict__ C, int M, int N, int K,
    int lda, int ldb, int ldc, const float* __restrict__ bias)
{
    constexpr int WM = BM / WRM;        // warp tile M
    constexpr int WN = BN / WRN;        // warp tile N
    constexpr int MI = WM / 16;         // mma tiles per warp (M)
    constexpr int NI = WN / 8;          // mma tiles per warp (N)
    constexpr int PAD = 4;

    __shared__ float As[BM][BK + PAD];
    __shared__ float Bs[BN][BK + PAD];

    const int tid  = threadIdx.x;
    const int lane = tid & 31;
    const int warp = tid >> 5;
    const int wm = (warp % WRM) * WM;
    const int wn = (warp / WRM) * WN;
    const int m0 = blockIdx.y * BM;
    const int n0 = blockIdx.x * BN;
    const int g  = lane >> 2;           // group id (0..7)
    const int tg = lane & 3;            // thread-in-group (0..3)

    float acc[MI][NI][4];
#pragma unroll
    for (int mi = 0; mi < MI; mi++)
#pragma unroll
        for (int ni = 0; ni < NI; ni++)
#pragma unroll
            for (int j = 0; j < 4; j++) acc[mi][ni][j] = 0.f;

    for (int k0 = 0; k0 < K; k0 += BK) {
        // ---- global -> smem (convert to tf32 once here) ----
#pragma unroll
        for (int i = tid * 4; i < BM * BK; i += 256 * 4) {
            int m = i / BK, k = i % BK;
            float4 v = *(const float4*)&A[(size_t)(m0 + m) * lda + k0 + k];
            unsigned* dst = (unsigned*)&As[m][k];
            dst[0] = f2tf32(v.x); dst[1] = f2tf32(v.y);
            dst[2] = f2tf32(v.z); dst[3] = f2tf32(v.w);
        }
#pragma unroll
        for (int i = tid * 4; i < BN * BK; i += 256 * 4) {
            int n = i / BK, k = i % BK;
            int gn = n0 + n;
            float4 v = make_float4(0.f, 0.f, 0.f, 0.f);
            if (gn < N) v = *(const float4*)&Bw[(size_t)gn * ldb + k0 + k];
            unsigned* dst = (unsigned*)&Bs[n][k];
            dst[0] = f2tf32(v.x); dst[1] = f2tf32(v.y);
            dst[2] = f2tf32(v.z); dst[3] = f2tf32(v.w);
        }
        __syncthreads();

#pragma unroll
        for (int kk = 0; kk < BK; kk += 8) {
            unsigned af[MI][4], bf[NI][2];
#pragma unroll
            for (int mi = 0; mi < MI; mi++) {
                int r = wm + mi * 16;
                af[mi][0] = __float_as_uint(As[r + g][kk + tg]);
                af[mi][1] = __float_as_uint(As[r + 8 + g][kk + tg]);
                af[mi][2] = __float_as_uint(As[r + g][kk + 4 + tg]);
                af[mi][3] = __float_as_uint(As[r + 8 + g][kk + 4 + tg]);
            }
#pragma unroll
            for (int ni = 0; ni < NI; ni++) {
                int c = wn + ni * 8 + g;
                bf[ni][0] = __float_as_uint(Bs[c][kk + tg]);
                bf[ni][1] = __float_as_uint(Bs[c][kk + 4 + tg]);
            }
#pragma unroll
            for (int mi = 0; mi < MI; mi++)
#pragma unroll
                for (int ni = 0; ni < NI; ni++)
                    mma_tf32(acc[mi][ni], af[mi], bf[ni]);
        }
        __syncthreads();
    }

    // ---- epilogue ----
#pragma unroll
    for (int mi = 0; mi < MI; mi++) {
#pragma unroll
        for (int ni = 0; ni < NI; ni++) {
#pragma unroll
            for (int j = 0; j < 4; j++) {
                int row = m0 + wm + mi * 16 + g + ((j >> 1) ? 8 : 0);
                int col = n0 + wn + ni * 8 + tg * 2 + (j & 1);
                if (col < N) {
                    float v = acc[mi][ni][j];
                    if (EPI == 1) {
                        v += bias[col];
                        v = (v > 20.f) ? v : log1pf(expf(v));
                    }
                    C[(size_t)row * ldc + col] = v;
                }
            }
        }
    }
}

// ---------------------------------------------------------------------------
// Causal depthwise conv1d (W=4) + bias + SiLU.
// ---------------------------------------------------------------------------
__global__ void conv_silu_kernel(const float* __restrict__ xz,
                                 const float* __restrict__ cw,
                                 const float* __restrict__ cb,
                                 float* __restrict__ xc)
{
    int idx = blockIdx.x * blockDim.x + threadIdx.x;
    if (idx >= MTOK * DI) return;
    int c = idx % DI;
    int t = idx / DI;        // global token index (b*L + l)
    int l = t % L_;

    float s = cb[c];
    const float* w = cw + c * 4;
#pragma unroll
    for (int j = 0; j < 4; j++) {
        int ll = l - 3 + j;
        if (ll >= 0)
            s = fmaf(w[j], xz[(size_t)(t - 3 + j) * (2 * DI) + c], s);
    }
    float sig = 1.f / (1.f + __expf(-s));
    xc[idx] = s * sig;
}

// ---------------------------------------------------------------------------
// Selective scan, fused with y += x*D and gating y *= silu(z).
// Block = 256 threads = 16 channels x 16 states; no barriers in time loop.
// grid = (DI/16, B)
// ---------------------------------------------------------------------------
__global__ void __launch_bounds__(256) scan_kernel(
    const float* __restrict__ xdbl, const float* __restrict__ delta,
    const float* __restrict__ xc,   const float* __restrict__ xz,
    const float* __restrict__ A_log, const float* __restrict__ Dp,
    float* __restrict__ g)
{
    const int b = blockIdx.y;
    const int c = blockIdx.x * 16 + (threadIdx.x >> 4);
    const int n = threadIdx.x & 15;

    const float Av = -__expf(A_log[c * DS + n]);
    const float Dv = Dp[c];

    const float* dptr = delta + (size_t)b * L_ * DI + c;
    const float* xptr = xc    + (size_t)b * L_ * DI + c;
    const float* bptr = xdbl  + (size_t)b * L_ * XD + DR + n;
    const float* cptr = xdbl  + (size_t)b * L_ * XD + DR + DS + n;
    const float* zptr = xz    + (size_t)b * L_ * (2 * DI) + DI + c;
    float*       gptr = g     + (size_t)b * L_ * DI + c;

    float h = 0.f;
    for (int t = 0; t < L_; t++) {
        float dt = *dptr;
        float xv = *xptr;
        float Bv = *bptr;
        float Cv = *cptr;

        float dA = __expf(dt * Av);
        h = fmaf(dA, h, dt * Bv * xv);

        float p = h * Cv;
        p += __shfl_xor_sync(0xffffffffu, p, 8, 16);
        p += __shfl_xor_sync(0xffffffffu, p, 4, 16);
        p += __shfl_xor_sync(0xffffffffu, p, 2, 16);
        p += __shfl_xor_sync(0xffffffffu, p, 1, 16);

        if (n == 0) {
            float y = p + xv * Dv;
            float z = *zptr;
            float sg = 1.f / (1.f + __expf(-z));
            *gptr = y * z * sg;
        }
        dptr += DI; xptr += DI; bptr += XD; cptr += XD;
        zptr += 2 * DI; gptr += DI;
    }
}

// ---------------------------------------------------------------------------
extern "C" void kernel_launch(void* const* d_in, const int* in_sizes, int n_in,
                              void* d_out, int out_size)
{
    const float* x          = (const float*)d_in[0];
    const float* in_proj_w  = (const float*)d_in[1];
    const float* conv_w     = (const float*)d_in[2];
    const float* conv_b     = (const float*)d_in[3];
    const float* x_proj_w   = (const float*)d_in[4];
    const float* dt_proj_w  = (const float*)d_in[5];
    const float* dt_proj_b  = (const float*)d_in[6];
    const float* A_log      = (const float*)d_in[7];
    const float* Dp         = (const float*)d_in[8];
    const float* out_proj_w = (const float*)d_in[9];
    float* out = (float*)d_out;

    float *xz, *xc, *xdbl, *delta, *gg;
    cudaGetSymbolAddress((void**)&xz,    g_xz);
    cudaGetSymbolAddress((void**)&xc,    g_xc);
    cudaGetSymbolAddress((void**)&xdbl,  g_xdbl);
    cudaGetSymbolAddress((void**)&delta, g_delta);
    cudaGetSymbolAddress((void**)&gg,    g_g);

    // 1) xz = x @ in_proj_w^T   [4096,1024] x [4096,1024]^T -> [4096,4096]
    mma_gemm_nt<128, 128, 32, 2, 4, 0><<<dim3(32, 32), 256>>>(
        x, in_proj_w, xz, MTOK, 2 * DI, DM, DM, DM, 2 * DI, nullptr);

    // 2) causal depthwise conv + SiLU -> xc
    conv_silu_kernel<<<(MTOK * DI + 255) / 256, 256>>>(xz, conv_w, conv_b, xc);

    // 3) x_dbl = xc @ x_proj_w^T  [4096,2048] x [96,2048]^T -> [4096,96]
    mma_gemm_nt<64, 96, 32, 4, 2, 0><<<dim3(1, 64), 256>>>(
        xc, x_proj_w, xdbl, MTOK, XD, DI, DI, DI, XD, nullptr);

    // 4) delta = softplus(x_dbl[:, :64] @ dt_proj_w^T + b)  -> [4096,2048]
    mma_gemm_nt<128, 128, 32, 2, 4, 1><<<dim3(16, 32), 256>>>(
        xdbl, dt_proj_w, delta, MTOK, DI, DR, XD, DR, DI, dt_proj_b);

    // 5) selective scan + skip(D) + gating silu(z) -> gg
    scan_kernel<<<dim3(DI / 16, B_), 256>>>(xdbl, delta, xc, xz, A_log, Dp, gg);

    // 6) out = gg @ out_proj_w^T  [4096,2048] x [1024,2048]^T -> [4096,1024]
    mma_gemm_nt<128, 128, 32, 2, 4, 0><<<dim3(8, 32), 256>>>(
        gg, out_proj_w, out, MTOK, DM, DI, DI, DI, DM, nullptr);
}

// round 10
// speedup vs baseline: 4.1902x; 2.6140x over previous
#include <cuda_runtime.h>
#include <math.h>

// Problem constants
#define B_    2
#define L_    2048
#define DM    1024
#define DI    2048
#define DS    16
#define DR    64
#define XD    96            // DR + 2*DS
#define MTOK  (B_ * L_)     // 4096 tokens

// Scratch (device globals: allocation-free)
__device__ float g_xz[(size_t)MTOK * (2 * DI)];   // [M, 4096]  in-proj output (x_p | z)
__device__ float g_xc[(size_t)MTOK * DI];         // [M, 2048]  conv+silu output
__device__ float g_xdbl[(size_t)MTOK * XD];       // [M, 96]    (dt_raw | B | C)
__device__ float g_delta[(size_t)MTOK * DI];      // [M, 2048]  softplus(dt)
__device__ float g_g[(size_t)MTOK * DI];          // [M, 2048]  gated scan output

// ---------------------------------------------------------------------------
// TF32 helpers
// ---------------------------------------------------------------------------
__device__ __forceinline__ unsigned f2tf32(float f) {
    unsigned r;
    asm("cvt.rna.tf32.f32 %0, %1;" : "=r"(r) : "f"(f));
    return r;
}

__device__ __forceinline__ void mma_tf32(float (&d)[4], const unsigned (&a)[4],
                                         const unsigned (&b)[2]) {
    asm volatile(
        "mma.sync.aligned.m16n8k8.row.col.f32.tf32.tf32.f32 "
        "{%0,%1,%2,%3}, {%4,%5,%6,%7}, {%8,%9}, {%0,%1,%2,%3};\n"
        : "+f"(d[0]), "+f"(d[1]), "+f"(d[2]), "+f"(d[3])
        : "r"(a[0]), "r"(a[1]), "r"(a[2]), "r"(a[3]),
          "r"(b[0]), "r"(b[1]));
}

// ---------------------------------------------------------------------------
// TF32 tensor-core GEMM: C[M,N] = A[M,K] @ B[N,K]^T  (both K-contiguous, "NT")
// Double-buffered smem, register-staged global prefetch, one sync per tile.
// Conflict-free smem: row stride (BK+4) floats -> fragment LDS bank = lane id.
// 256 threads, 8 warps (WRM x WRN). Exact tiling assumed:
// M%BM==0, N%BN==0, K%BK==0.  EPI=0: plain. EPI=1: +=bias, softplus.
// ---------------------------------------------------------------------------
template <int BM, int BN, int BK, int WRM, int WRN, int EPI>
__global__ void __launch_bounds__(256) mma_gemm_nt(
    const float* __restrict__ A, const float* __restrict__ Bw,
    float* __restrict__ C, int M, int N, int K,
    int lda, int ldb, int ldc, const float* __restrict__ bias)
{
    constexpr int WM = BM / WRM, WN = BN / WRN;
    constexpr int MI = WM / 16, NI = WN / 8;
    constexpr int LDSZ = BK + 4;
    constexpr int K4 = BK / 4;
    constexpr int AF4 = BM * K4;                 // float4 elements in A tile
    constexpr int BF4 = BN * K4;
    constexpr int AP = (AF4 + 255) / 256;
    constexpr int BP = (BF4 + 255) / 256;

    __shared__ float As[2][BM][LDSZ];
    __shared__ float Bs[2][BN][LDSZ];

    const int tid  = threadIdx.x;
    const int lane = tid & 31;
    const int warp = tid >> 5;
    const int wm = (warp % WRM) * WM;
    const int wn = (warp / WRM) * WN;
    const int m0 = blockIdx.y * BM;
    const int n0 = blockIdx.x * BN;
    const int g  = lane >> 2;           // 0..7
    const int tg = lane & 3;            // 0..3

    float4 ar[AP], br[BP];

    auto load_ab = [&](int k0) {
#pragma unroll
        for (int p = 0; p < AP; p++) {
            int i = tid + p * 256;
            if ((AF4 % 256 == 0) || i < AF4)
                ar[p] = *(const float4*)&A[(size_t)(m0 + i / K4) * lda + k0 + (i % K4) * 4];
        }
#pragma unroll
        for (int p = 0; p < BP; p++) {
            int i = tid + p * 256;
            if ((BF4 % 256 == 0) || i < BF4)
                br[p] = *(const float4*)&Bw[(size_t)(n0 + i / K4) * ldb + k0 + (i % K4) * 4];
        }
    };
    auto store_ab = [&](int s) {
#pragma unroll
        for (int p = 0; p < AP; p++) {
            int i = tid + p * 256;
            if ((AF4 % 256 == 0) || i < AF4) {
                unsigned* d = (unsigned*)&As[s][i / K4][(i % K4) * 4];
                d[0] = f2tf32(ar[p].x); d[1] = f2tf32(ar[p].y);
                d[2] = f2tf32(ar[p].z); d[3] = f2tf32(ar[p].w);
            }
        }
#pragma unroll
        for (int p = 0; p < BP; p++) {
            int i = tid + p * 256;
            if ((BF4 % 256 == 0) || i < BF4) {
                unsigned* d = (unsigned*)&Bs[s][i / K4][(i % K4) * 4];
                d[0] = f2tf32(br[p].x); d[1] = f2tf32(br[p].y);
                d[2] = f2tf32(br[p].z); d[3] = f2tf32(br[p].w);
            }
        }
    };

    float acc[MI][NI][4];
#pragma unroll
    for (int mi = 0; mi < MI; mi++)
#pragma unroll
        for (int ni = 0; ni < NI; ni++)
#pragma unroll
            for (int j = 0; j < 4; j++) acc[mi][ni][j] = 0.f;

    load_ab(0);
    store_ab(0);
    __syncthreads();

    const int nt = K / BK;
#pragma unroll 1
    for (int t = 0; t < nt; t++) {
        const int s = t & 1;
        if (t + 1 < nt) load_ab((t + 1) * BK);

#pragma unroll
        for (int kk = 0; kk < BK; kk += 8) {
            unsigned af[MI][4], bf[NI][2];
#pragma unroll
            for (int mi = 0; mi < MI; mi++) {
                const int r = wm + mi * 16;
                af[mi][0] = __float_as_uint(As[s][r + g][kk + tg]);
                af[mi][1] = __float_as_uint(As[s][r + 8 + g][kk + tg]);
                af[mi][2] = __float_as_uint(As[s][r + g][kk + 4 + tg]);
                af[mi][3] = __float_as_uint(As[s][r + 8 + g][kk + 4 + tg]);
            }
#pragma unroll
            for (int ni = 0; ni < NI; ni++) {
                const int cn = wn + ni * 8 + g;
                bf[ni][0] = __float_as_uint(Bs[s][cn][kk + tg]);
                bf[ni][1] = __float_as_uint(Bs[s][cn][kk + 4 + tg]);
            }
#pragma unroll
            for (int mi = 0; mi < MI; mi++)
#pragma unroll
                for (int ni = 0; ni < NI; ni++)
                    mma_tf32(acc[mi][ni], af[mi], bf[ni]);
        }

        if (t + 1 < nt) store_ab(s ^ 1);
        __syncthreads();
    }

    // Epilogue: float2 stores (cols tg*2, tg*2+1 are adjacent)
#pragma unroll
    for (int mi = 0; mi < MI; mi++) {
#pragma unroll
        for (int ni = 0; ni < NI; ni++) {
#pragma unroll
            for (int half = 0; half < 2; half++) {
                int row = m0 + wm + mi * 16 + g + half * 8;
                int col = n0 + wn + ni * 8 + tg * 2;
                float v0 = acc[mi][ni][half * 2 + 0];
                float v1 = acc[mi][ni][half * 2 + 1];
                if (EPI == 1) {
                    v0 += bias[col];
                    v1 += bias[col + 1];
                    v0 = (v0 > 20.f) ? v0 : log1pf(expf(v0));
                    v1 = (v1 > 20.f) ? v1 : log1pf(expf(v1));
                }
                *(float2*)&C[(size_t)row * ldc + col] = make_float2(v0, v1);
            }
        }
    }
}

// ---------------------------------------------------------------------------
// Causal depthwise conv1d (W=4) + bias + SiLU, vectorized over 4 channels.
// ---------------------------------------------------------------------------
__global__ void conv_silu_kernel(const float* __restrict__ xz,
                                 const float* __restrict__ cw,
                                 const float* __restrict__ cb,
                                 float* __restrict__ xc)
{
    int idx = blockIdx.x * blockDim.x + threadIdx.x;   // over MTOK*DI/4
    if (idx >= MTOK * DI / 4) return;
    int c4 = idx % (DI / 4);
    int t  = idx / (DI / 4);
    int l  = t % L_;
    int c  = c4 * 4;

    float4 w0 = *(const float4*)&cw[(c + 0) * 4];
    float4 w1 = *(const float4*)&cw[(c + 1) * 4];
    float4 w2 = *(const float4*)&cw[(c + 2) * 4];
    float4 w3 = *(const float4*)&cw[(c + 3) * 4];
    float4 bb = *(const float4*)&cb[c];
    float s0 = bb.x, s1 = bb.y, s2 = bb.z, s3 = bb.w;

#pragma unroll
    for (int j = 0; j < 4; j++) {
        if (l - 3 + j >= 0) {
            float4 v = *(const float4*)&xz[(size_t)(t - 3 + j) * (2 * DI) + c];
            s0 = fmaf(((const float*)&w0)[j], v.x, s0);
            s1 = fmaf(((const float*)&w1)[j], v.y, s1);
            s2 = fmaf(((const float*)&w2)[j], v.z, s2);
            s3 = fmaf(((const float*)&w3)[j], v.w, s3);
        }
    }
    float4 o;
    o.x = s0 * (1.f / (1.f + __expf(-s0)));
    o.y = s1 * (1.f / (1.f + __expf(-s1)));
    o.z = s2 * (1.f / (1.f + __expf(-s2)));
    o.w = s3 * (1.f / (1.f + __expf(-s3)));
    *(float4*)&xc[(size_t)t * DI + c] = o;
}

// ---------------------------------------------------------------------------
// Selective scan + skip(D) + gating silu(z).
// Block = 64 threads = 16 channels x 4 state-groups (4 states per thread).
// Inputs for a 32-step time chunk are staged into smem with coalesced float4
// loads; the inner loop is pure smem + MUFU + FFMA + 2 narrow shfls.
// grid = (DI/16, B)
// ---------------------------------------------------------------------------
#define TC 32

__global__ void __launch_bounds__(64) scan_kernel(
    const float* __restrict__ xdbl, const float* __restrict__ delta,
    const float* __restrict__ xc,   const float* __restrict__ xz,
    const float* __restrict__ A_log, const float* __restrict__ Dp,
    float* __restrict__ g)
{
    const int b   = blockIdx.y;
    const int c0  = blockIdx.x * 16;
    const int tid = threadIdx.x;
    const int ci  = tid >> 2;          // channel within block (0..15)
    const int c   = c0 + ci;
    const int sg  = tid & 3;           // state group (0..3)
    const int n0  = sg * 4;

    __shared__ float s_dt[TC][16], s_xv[TC][16], s_z[TC][16];
    __shared__ float s_B[TC][16], s_C[TC][16];

    float Av0 = -__expf(A_log[c * DS + n0 + 0]);
    float Av1 = -__expf(A_log[c * DS + n0 + 1]);
    float Av2 = -__expf(A_log[c * DS + n0 + 2]);
    float Av3 = -__expf(A_log[c * DS + n0 + 3]);
    const float Dv = Dp[c];

    float h0 = 0.f, h1 = 0.f, h2 = 0.f, h3 = 0.f;
    const size_t rowb = (size_t)b * L_;

    for (int t0 = 0; t0 < L_; t0 += TC) {
        __syncthreads();   // previous chunk fully consumed before overwrite
        // stage dt, xv, z: TC*16 floats each = 128 float4 -> 2 per thread
#pragma unroll
        for (int p = 0; p < 2; p++) {
            int i  = tid + p * 64;
            int tt = i >> 2, q = (i & 3) * 4;
            size_t r = rowb + t0 + tt;
            *(float4*)&s_dt[tt][q] = *(const float4*)&delta[r * DI + c0 + q];
            *(float4*)&s_xv[tt][q] = *(const float4*)&xc[r * DI + c0 + q];
            *(float4*)&s_z [tt][q] = *(const float4*)&xz[r * (2 * DI) + DI + c0 + q];
        }
        // stage B,C: 32 floats per step (contiguous in xdbl) = 256 float4 total
#pragma unroll
        for (int p = 0; p < 4; p++) {
            int i  = tid + p * 64;
            int tt = i >> 3, q = i & 7;
            float4 v = *(const float4*)&xdbl[(rowb + t0 + tt) * XD + DR + q * 4];
            if (q < 4) *(float4*)&s_B[tt][q * 4] = v;
            else       *(float4*)&s_C[tt][(q - 4) * 4] = v;
        }
        __syncthreads();

#pragma unroll 4
        for (int tt = 0; tt < TC; tt++) {
            float dt = s_dt[tt][ci];
            float xv = s_xv[tt][ci];
            float u  = dt * xv;
            float4 Bv = *(const float4*)&s_B[tt][n0];
            float4 Cv = *(const float4*)&s_C[tt][n0];

            h0 = fmaf(__expf(dt * Av0), h0, u * Bv.x);
            h1 = fmaf(__expf(dt * Av1), h1, u * Bv.y);
            h2 = fmaf(__expf(dt * Av2), h2, u * Bv.z);
            h3 = fmaf(__expf(dt * Av3), h3, u * Bv.w);

            float p = fmaf(h0, Cv.x, fmaf(h1, Cv.y, fmaf(h2, Cv.z, h3 * Cv.w)));
            p += __shfl_xor_sync(0xffffffffu, p, 1, 4);
            p += __shfl_xor_sync(0xffffffffu, p, 2, 4);

            if (sg == 0) {
                float z = s_z[tt][ci];
                float y = p + xv * Dv;
                g[(rowb + t0 + tt) * DI + c] = y * z * (1.f / (1.f + __expf(-z)));
            }
        }
    }
}

// ---------------------------------------------------------------------------
extern "C" void kernel_launch(void* const* d_in, const int* in_sizes, int n_in,
                              void* d_out, int out_size)
{
    const float* x          = (const float*)d_in[0];
    const float* in_proj_w  = (const float*)d_in[1];
    const float* conv_w     = (const float*)d_in[2];
    const float* conv_b     = (const float*)d_in[3];
    const float* x_proj_w   = (const float*)d_in[4];
    const float* dt_proj_w  = (const float*)d_in[5];
    const float* dt_proj_b  = (const float*)d_in[6];
    const float* A_log      = (const float*)d_in[7];
    const float* Dp         = (const float*)d_in[8];
    const float* out_proj_w = (const float*)d_in[9];
    float* out = (float*)d_out;

    float *xz, *xc, *xdbl, *delta, *gg;
    cudaGetSymbolAddress((void**)&xz,    g_xz);
    cudaGetSymbolAddress((void**)&xc,    g_xc);
    cudaGetSymbolAddress((void**)&xdbl,  g_xdbl);
    cudaGetSymbolAddress((void**)&delta, g_delta);
    cudaGetSymbolAddress((void**)&gg,    g_g);

    // 1) xz = x @ in_proj_w^T   [4096,1024] x [4096,1024]^T -> [4096,4096]
    mma_gemm_nt<128, 128, 16, 2, 4, 0><<<dim3(32, 32), 256>>>(
        x, in_proj_w, xz, MTOK, 2 * DI, DM, DM, DM, 2 * DI, nullptr);

    // 2) causal depthwise conv + SiLU -> xc
    conv_silu_kernel<<<(MTOK * DI / 4 + 255) / 256, 256>>>(xz, conv_w, conv_b, xc);

    // 3) x_dbl = xc @ x_proj_w^T  [4096,2048] x [96,2048]^T -> [4096,96]
    mma_gemm_nt<64, 96, 16, 2, 4, 0><<<dim3(1, 64), 256>>>(
        xc, x_proj_w, xdbl, MTOK, XD, DI, DI, DI, XD, nullptr);

    // 4) delta = softplus(x_dbl[:, :64] @ dt_proj_w^T + b)  -> [4096,2048]
    mma_gemm_nt<128, 128, 16, 2, 4, 1><<<dim3(16, 32), 256>>>(
        xdbl, dt_proj_w, delta, MTOK, DI, DR, XD, DR, DI, dt_proj_b);

    // 5) selective scan + skip(D) + gating silu(z) -> gg
    scan_kernel<<<dim3(DI / 16, B_), 64>>>(xdbl, delta, xc, xz, A_log, Dp, gg);

    // 6) out = gg @ out_proj_w^T  [4096,2048] x [1024,2048]^T -> [4096,1024]
    mma_gemm_nt<128, 128, 16, 2, 4, 0><<<dim3(8, 32), 256>>>(
        gg, out_proj_w, out, MTOK, DM, DI, DI, DI, DM, nullptr);
}